// round 10
// baseline (speedup 1.0000x reference)
#include <cuda_runtime.h>
#include <math.h>

#define DD 512
#define NN 128
#define TB 8

typedef unsigned long long ull;

__device__ float g_picked[NN];

// ---- packed f32x2 helpers (Blackwell FFMA2 path, PTX-only) -----------------
static __device__ __forceinline__ ull ffma2(ull a, ull b, ull c)
{
    ull d;
    asm("fma.rn.f32x2 %0, %1, %2, %3;" : "=l"(d) : "l"(a), "l"(b), "l"(c));
    return d;
}
static __device__ __forceinline__ ull pack2(float x, float y)
{
    ull d;
    asm("mov.b64 %0, {%1, %2};" : "=l"(d) : "f"(x), "f"(y));
    return d;
}
static __device__ __forceinline__ void unpack2(ull v, float& x, float& y)
{
    asm("mov.b64 {%0, %1}, %2;" : "=f"(x), "=f"(y) : "l"(v));
}

// ---------------------------------------------------------------------------
// One CTA (512 threads, 16 warps) per output row k.
// Omega (128x128) register-resident:
//   warp w covers rows [8w, 8w+8); lane: row = 8w + (lane>>2),
//   cg = lane&3 -> cols [32cg, 32cg+32) as 16 packed f32x2 registers.
// Per TB=8-site block:
//   phase1: w_b[row] partial dot (8 LDS.128 + 16 ffma2) + 2-stage butterfly
//           (shfl xor 1,2); cg0 lanes publish wfin.             [b1]
//   gram:   S[a][b] = p_a . w_b  (16 warps x 4 entries)         [b2]
//   LU:     8x8 LU on S by WARP 0 ONLY; publishes L_s, rd_s;
//           lane0 emits probs.                                  [b3]
//   fwdsub: y_j = w_j - sum L_s[j][m] y_m  in registers (L via
//           broadcast LDS); cg0 lanes publish Y_s.              [b4]
//   update: Omega[row][c] -= (y_j[row]*rd_j) * y_j[c]
// ---------------------------------------------------------------------------
__global__ void __launch_bounds__(512, 1)
sampler_kernel(const float* __restrict__ P, const int* __restrict__ pos,
               float* __restrict__ out)
{
    __shared__ __align__(16) float pv_s[2][TB][NN];
    __shared__ __align__(16) float wfin[TB][NN];
    __shared__ __align__(16) float Y_s[TB][NN];
    __shared__ __align__(16) float S_s[64];
    __shared__ float L_s[TB][TB];
    __shared__ float rd_s[TB];
    __shared__ unsigned char occ[DD];

    const int k    = blockIdx.x;
    const int tid  = threadIdx.x;
    const int lane = tid & 31;
    const int wid  = tid >> 5;               // 0..15
    const int row  = wid * 8 + (lane >> 2);  // 0..127
    const int cg   = lane & 3;
    const int c0   = cg * 32;

    if (tid < DD) occ[tid] = 0;
    __syncthreads();
    if (tid < NN) occ[pos[tid]] = 1;

    const int myPos = pos[k];
    const int xmin  = (k == 0) ? 0 : (pos[k - 1] + 1);
    const int xmax  = DD - NN + k + 1;

    if (tid < DD) out[k * DD + tid] = 0.0f;

    // Omega = I : A2[t] covers (row, cols c0+2t, c0+2t+1)
    ull A2[16];
#pragma unroll
    for (int t = 0; t < 16; t++)
        A2[t] = pack2((row == c0 + 2 * t) ? 1.0f : 0.0f,
                      (row == c0 + 2 * t + 1) ? 1.0f : 0.0f);

    // stage first block's 8 P rows: 1024 floats = 256 float4
    if (tid < 256) ((float4*)&pv_s[0][0][0])[tid] = __ldg((const float4*)P + tid);
    __syncthreads();

    float cprod = 1.0f;        // meaningful in warp 0 only
    int buf = 0;
    for (int i0 = 0; i0 < xmax; i0 += TB) {
        const bool last = (i0 + TB >= xmax);

        float4 pf;
        if (tid < 256 && !last)
            pf = __ldg((const float4*)(P + (i0 + TB) * NN) + tid);

        // ---- phase1: per b, 32-col partial dot + 2-stage butterfly
        float wreg[TB];
#pragma unroll
        for (int b = 0; b < TB; b++) {
            const ulonglong2* pb = (const ulonglong2*)&pv_s[buf][b][c0];
            ull a0 = 0ull, a1 = 0ull, a2 = 0ull, a3 = 0ull;
#pragma unroll
            for (int t = 0; t < 8; t += 2) {
                ulonglong2 u = pb[t];
                ulonglong2 v = pb[t + 1];
                a0 = ffma2(A2[2 * t],     u.x, a0);
                a1 = ffma2(A2[2 * t + 1], u.y, a1);
                a2 = ffma2(A2[2 * t + 2], v.x, a2);
                a3 = ffma2(A2[2 * t + 3], v.y, a3);
            }
            float x0, y0, x1, y1, x2, y2, x3, y3;
            unpack2(a0, x0, y0); unpack2(a1, x1, y1);
            unpack2(a2, x2, y2); unpack2(a3, x3, y3);
            float wb = ((x0 + y0) + (x1 + y1)) + ((x2 + y2) + (x3 + y3));
            wb += __shfl_xor_sync(0xffffffffu, wb, 1);
            wb += __shfl_xor_sync(0xffffffffu, wb, 2);
            wreg[b] = wb;
            if (cg == 0) wfin[b][row] = wb;
        }
        if (tid < 256 && !last)
            ((float4*)&pv_s[buf ^ 1][0][0])[tid] = pf;
        __syncthreads();                               // --- b1 ---

        // ---- Gram: 16 warps x 4 entries; S[a][b] = sum_r p_a[r] w_b[r]
        {
            const int e0 = wid * 4;
            float tacc[4];
#pragma unroll
            for (int e = 0; e < 4; e++) {
                int a = (e0 + e) >> 3, b = (e0 + e) & 7;
                float4 pa = ((const float4*)&pv_s[buf][a][0])[lane];
                float4 wb4 = ((const float4*)&wfin[b][0])[lane];
                tacc[e] = pa.x * wb4.x + pa.y * wb4.y + pa.z * wb4.z + pa.w * wb4.w;
            }
#pragma unroll
            for (int off = 16; off; off >>= 1) {
#pragma unroll
                for (int e = 0; e < 4; e++)
                    tacc[e] += __shfl_xor_sync(0xffffffffu, tacc[e], off);
            }
            if (lane == 0)
                *(float4*)&S_s[e0] = make_float4(tacc[0], tacc[1], tacc[2], tacc[3]);
        }
        __syncthreads();                               // --- b2 ---

        // ---- LU on warp 0 only; publish L_s, rd_s; lane0 emits probs
        const int Teff = last ? (xmax - i0) : TB;
        if (wid == 0) {
            float S_row[TB];
#pragma unroll
            for (int b = 0; b < TB; b++)
                S_row[b] = (lane < TB) ? S_s[lane * TB + b] : 0.0f;
            float cp = cprod;
#pragma unroll
            for (int j = 0; j < TB; j++) {
                if (j >= Teff) break;
                float rj[TB];
#pragma unroll
                for (int b = 0; b < TB; b++)
                    rj[b] = __shfl_sync(0xffffffffu, S_row[b], j);
                const float beta = rj[j];
                const int i = i0 + j;
                const bool inwin = (i >= xmin);
                if (lane == 0 && inwin) {
                    float prob = cp * beta;
                    float pcl = (fabsf(prob) > 1e-15f) ? prob : 0.0f;
                    out[k * DD + i] = pcl;
                    if (i == myPos) g_picked[k] = pcl;
                }
                if (inwin) cp *= (1.0f - beta);
                if (i == xmax - 1) break;  // forced last site: no elimination
                const float d  = (!inwin && occ[i]) ? beta : (beta - 1.0f);
                const float rd = 1.0f / d;
                const float mult = S_row[j] * rd;   // = L[lane][j] (symmetry)
                if (lane < TB) L_s[lane][j] = mult;
                if (lane == 0) rd_s[j] = rd;
#pragma unroll
                for (int b = 0; b < TB; b++)
                    S_row[b] = fmaf(-mult, rj[b], S_row[b]);
            }
            cprod = cp;
        }
        __syncthreads();                               // --- b3 ---
        if (last) break;

        // ---- forward substitution in registers (y aliases wreg):
        //      y_j = w_j - sum_{m<j} L_s[j][m] y_m   (L via broadcast LDS)
#pragma unroll
        for (int j = 1; j < TB; j++) {
#pragma unroll
            for (int m = 0; m < j; m++)
                wreg[j] = fmaf(-L_s[j][m], wreg[m], wreg[j]);
        }
        if (cg == 0) {
#pragma unroll
            for (int j = 0; j < TB; j++) Y_s[j][row] = wreg[j];
        }
        __syncthreads();                               // --- b4 ---

        // ---- rank-8 update: Omega[row][c] -= (y_j[row]*rd_j) * y_j[c]
#pragma unroll
        for (int j = 0; j < TB; j++) {
            float nz = -(wreg[j] * rd_s[j]);
            ull nz2 = pack2(nz, nz);
            const ulonglong2* yb = (const ulonglong2*)&Y_s[j][c0];
#pragma unroll
            for (int t = 0; t < 8; t += 2) {
                ulonglong2 u = yb[t];
                ulonglong2 v = yb[t + 1];
                A2[2 * t]     = ffma2(nz2, u.x, A2[2 * t]);
                A2[2 * t + 1] = ffma2(nz2, u.y, A2[2 * t + 1]);
                A2[2 * t + 2] = ffma2(nz2, v.x, A2[2 * t + 2]);
                A2[2 * t + 3] = ffma2(nz2, v.y, A2[2 * t + 3]);
            }
        }
        buf ^= 1;
    }
}

// ---------------------------------------------------------------------------
// Parallel log-sum of picked probabilities (one warp, tree reduction).
// ---------------------------------------------------------------------------
__global__ void logsum_kernel(float* __restrict__ out_scalar)
{
    int lane = threadIdx.x;
    float s = 0.0f;
    for (int k = lane; k < NN; k += 32) s += logf(g_picked[k]);
#pragma unroll
    for (int o = 16; o; o >>= 1) s += __shfl_xor_sync(0xffffffffu, s, o);
    if (lane == 0) *out_scalar = s;
}

extern "C" void kernel_launch(void* const* d_in, const int* in_sizes, int n_in,
                              void* d_out, int out_size)
{
    const float* P = (const float*)d_in[0];    // [D, N] float32
    const int* pos = (const int*)d_in[1];      // [N] int32, sorted
    float* out = (float*)d_out;                // [N*D probs][1 logprob]

    sampler_kernel<<<NN, 512>>>(P, pos, out);
    logsum_kernel<<<1, 32>>>(out + (out_size - 1));
}

// round 11
// speedup vs baseline: 4.3328x; 4.3328x over previous
#include <cuda_runtime.h>
#include <math.h>

#define DD 512
#define NN 128
#define TB 8

typedef unsigned long long ull;

__device__ float g_picked[NN];

// ---- packed f32x2 helpers (Blackwell FFMA2 path, PTX-only) -----------------
static __device__ __forceinline__ ull ffma2(ull a, ull b, ull c)
{
    ull d;
    asm("fma.rn.f32x2 %0, %1, %2, %3;" : "=l"(d) : "l"(a), "l"(b), "l"(c));
    return d;
}
static __device__ __forceinline__ ull pack2(float x, float y)
{
    ull d;
    asm("mov.b64 %0, {%1, %2};" : "=l"(d) : "f"(x), "f"(y));
    return d;
}
static __device__ __forceinline__ void unpack2(ull v, float& x, float& y)
{
    asm("mov.b64 {%0, %1}, %2;" : "=f"(x), "=f"(y) : "l"(v));
}

// ---------------------------------------------------------------------------
// One CTA (256 threads, 8 warps) per output row k.
// Omega (128x128) register-resident, 2 rows x 32 cols per thread:
//   warp w covers rows [16w,16w+16); lane: rgl=lane>>2 -> rows r0=16w+2rgl,
//   r0+1; cg=lane&3 -> INTERLEAVED col chunks: float4 chunks at cols
//   16q+4cg, q=0..7. The 4 cg groups of one q read 64 contiguous bytes ->
//   every broadcast LDS.128 is exactly 1 wavefront (no bank aliasing).
// Per TB=8-site block (structure identical to the validated R7 kernel):
//   phase1: w_b partial dot (8 LDS.128 shared by both rows, 32 ffma2)
//           + 2-stage butterfly (shfl xor 1,2) x 2 rows; cg0 -> wfin  [b1]
//   gram:   S[a][b] = p_a . w_b (warp a, shfl tree)                   [b2]
//   LU:     8x8 LU on S redundantly per warp; warp0 lane0 emits probs
//   fwdsub: y_j in registers (both rows share L shuffles); cg0 -> Y_s [b3]
//   update: Omega[row][c] -= (y_j[row]*rd_j)*y_j[c]  (8 LDS.128/j)
// ---------------------------------------------------------------------------
__global__ void __launch_bounds__(256, 1)
sampler_kernel(const float* __restrict__ P, const int* __restrict__ pos,
               float* __restrict__ out)
{
    __shared__ __align__(16) float pv_s[2][TB][NN];
    __shared__ __align__(16) float wfin[TB][NN];
    __shared__ __align__(16) float Y_s[TB][NN];
    __shared__ __align__(16) float S_s[64];
    __shared__ unsigned char occ[DD];

    const int k    = blockIdx.x;
    const int tid  = threadIdx.x;
    const int lane = tid & 31;
    const int wid  = tid >> 5;               // 0..7
    const int rgl  = lane >> 2;              // 0..7
    const int cg   = lane & 3;               // 0..3
    const int r0   = wid * 16 + rgl * 2;     // rows r0, r0+1

    for (int i = tid; i < DD; i += 256) occ[i] = 0;
    __syncthreads();
    if (tid < NN) occ[pos[tid]] = 1;

    const int myPos = pos[k];
    const int xmin  = (k == 0) ? 0 : (pos[k - 1] + 1);
    const int xmax  = DD - NN + k + 1;

    for (int i = tid; i < DD; i += 256) out[k * DD + i] = 0.0f;

    // Omega = I. A2[rr][2q]   covers (row r0+rr, cols 16q+4cg,   16q+4cg+1)
    //            A2[rr][2q+1] covers (row r0+rr, cols 16q+4cg+2, 16q+4cg+3)
    ull A2[2][16];
#pragma unroll
    for (int rr = 0; rr < 2; rr++) {
        const int row = r0 + rr;
#pragma unroll
        for (int q = 0; q < 8; q++) {
            const int cb = 16 * q + 4 * cg;
            A2[rr][2 * q]     = pack2((row == cb)     ? 1.0f : 0.0f,
                                      (row == cb + 1) ? 1.0f : 0.0f);
            A2[rr][2 * q + 1] = pack2((row == cb + 2) ? 1.0f : 0.0f,
                                      (row == cb + 3) ? 1.0f : 0.0f);
        }
    }

    // stage first block's 8 P rows: 1024 floats = 256 float4
    ((float4*)&pv_s[0][0][0])[tid] = __ldg((const float4*)P + tid);
    __syncthreads();

    float cprod = 1.0f;
    int buf = 0;
    for (int i0 = 0; i0 < xmax; i0 += TB) {
        const bool last = (i0 + TB >= xmax);

        float4 pf;
        if (!last) pf = __ldg((const float4*)(P + (i0 + TB) * NN) + tid);

        // ---- phase1: per b, 32-col partial dot for 2 rows + 2-stage butterfly
        float w0[TB], w1[TB];
#pragma unroll
        for (int b = 0; b < TB; b++) {
            const ulonglong2* pb = (const ulonglong2*)&pv_s[buf][b][0];
            ull a00 = 0ull, a01 = 0ull, a10 = 0ull, a11 = 0ull;
#pragma unroll
            for (int q = 0; q < 8; q++) {
                ulonglong2 u = pb[4 * q + cg];     // 1 wavefront (contig 64B x4cg)
                a00 = ffma2(A2[0][2 * q],     u.x, a00);
                a01 = ffma2(A2[0][2 * q + 1], u.y, a01);
                a10 = ffma2(A2[1][2 * q],     u.x, a10);
                a11 = ffma2(A2[1][2 * q + 1], u.y, a11);
            }
            float x0, y0, x1, y1;
            unpack2(a00, x0, y0); unpack2(a01, x1, y1);
            float s0 = (x0 + y0) + (x1 + y1);
            unpack2(a10, x0, y0); unpack2(a11, x1, y1);
            float s1 = (x0 + y0) + (x1 + y1);
            s0 += __shfl_xor_sync(0xffffffffu, s0, 1);
            s0 += __shfl_xor_sync(0xffffffffu, s0, 2);
            s1 += __shfl_xor_sync(0xffffffffu, s1, 1);
            s1 += __shfl_xor_sync(0xffffffffu, s1, 2);
            w0[b] = s0;
            w1[b] = s1;
            if (cg == 0) { wfin[b][r0] = s0; wfin[b][r0 + 1] = s1; }
        }
        if (!last) ((float4*)&pv_s[buf ^ 1][0][0])[tid] = pf;
        __syncthreads();                               // --- b1 ---

        // ---- Gram: warp 'wid' computes S[wid][b] = sum_r p_wid[r]*w_b[r]
        {
            float4 pa = ((const float4*)&pv_s[buf][wid][0])[lane];
            float sg[TB];
#pragma unroll
            for (int b = 0; b < TB; b++) {
                float4 wb4 = ((const float4*)&wfin[b][0])[lane];
                sg[b] = pa.x * wb4.x + pa.y * wb4.y + pa.z * wb4.z + pa.w * wb4.w;
            }
#pragma unroll
            for (int off = 16; off; off >>= 1) {
#pragma unroll
                for (int b = 0; b < TB; b++)
                    sg[b] += __shfl_xor_sync(0xffffffffu, sg[b], off);
            }
            if (lane == 0) {
                *(float4*)&S_s[wid * 8]     = make_float4(sg[0], sg[1], sg[2], sg[3]);
                *(float4*)&S_s[wid * 8 + 4] = make_float4(sg[4], sg[5], sg[6], sg[7]);
            }
        }
        __syncthreads();                               // --- b2 ---

        // ---- redundant warp-local 8x8 LU on S; lane a<8 holds row a of S
        const int Teff = last ? (xmax - i0) : TB;
        float S_row[TB];
        if (lane < TB) {
            float4 s0v = *(const float4*)&S_s[lane * 8];
            float4 s1v = *(const float4*)&S_s[lane * 8 + 4];
            S_row[0] = s0v.x; S_row[1] = s0v.y; S_row[2] = s0v.z; S_row[3] = s0v.w;
            S_row[4] = s1v.x; S_row[5] = s1v.y; S_row[6] = s1v.z; S_row[7] = s1v.w;
        } else {
#pragma unroll
            for (int b = 0; b < TB; b++) S_row[b] = 0.0f;
        }
        float Lcol[TB];
        float rdv[TB];
        float cp = cprod;
#pragma unroll
        for (int j = 0; j < TB; j++) {
            if (j >= Teff) break;
            float rj[TB];
#pragma unroll
            for (int b = 0; b < TB; b++)
                rj[b] = __shfl_sync(0xffffffffu, S_row[b], j);
            const float beta = rj[j];
            const int i = i0 + j;
            const bool inwin = (i >= xmin);
            if (wid == 0 && lane == 0 && inwin) {
                float prob = cp * beta;
                float pcl = (fabsf(prob) > 1e-15f) ? prob : 0.0f;
                out[k * DD + i] = pcl;
                if (i == myPos) g_picked[k] = pcl;
            }
            if (inwin) cp *= (1.0f - beta);
            if (i == xmax - 1) break;      // forced last site: no elimination
            const float d  = (!inwin && occ[i]) ? beta : (beta - 1.0f);
            const float rd = 1.0f / d;
            rdv[j] = rd;
            const float mult = S_row[j] * rd;   // = L[lane][j] (symmetry)
            Lcol[j] = mult;
#pragma unroll
            for (int b = 0; b < TB; b++)
                S_row[b] = fmaf(-mult, rj[b], S_row[b]);
        }
        cprod = cp;
        if (last) break;

        // ---- forward substitution in registers (y aliases w0/w1):
        //      y_j = w_j - sum_{m<j} L[j][m] y_m (one shfl serves both rows)
#pragma unroll
        for (int j = 1; j < TB; j++) {
#pragma unroll
            for (int m = 0; m < j; m++) {
                float ljm = __shfl_sync(0xffffffffu, Lcol[m], j);
                w0[j] = fmaf(-ljm, w0[m], w0[j]);
                w1[j] = fmaf(-ljm, w1[m], w1[j]);
            }
        }
        if (cg == 0) {
#pragma unroll
            for (int j = 0; j < TB; j++) {
                Y_s[j][r0]     = w0[j];
                Y_s[j][r0 + 1] = w1[j];
            }
        }
        __syncthreads();                               // --- b3 ---

        // ---- rank-8 update: Omega[row][c] -= (y_j[row]*rd_j) * y_j[c]
#pragma unroll
        for (int j = 0; j < TB; j++) {
            const float z0 = -(w0[j] * rdv[j]);
            const float z1 = -(w1[j] * rdv[j]);
            const ull nz0 = pack2(z0, z0);
            const ull nz1 = pack2(z1, z1);
            const ulonglong2* yb = (const ulonglong2*)&Y_s[j][0];
#pragma unroll
            for (int q = 0; q < 8; q++) {
                ulonglong2 u = yb[4 * q + cg];
                A2[0][2 * q]     = ffma2(nz0, u.x, A2[0][2 * q]);
                A2[0][2 * q + 1] = ffma2(nz0, u.y, A2[0][2 * q + 1]);
                A2[1][2 * q]     = ffma2(nz1, u.x, A2[1][2 * q]);
                A2[1][2 * q + 1] = ffma2(nz1, u.y, A2[1][2 * q + 1]);
            }
        }
        buf ^= 1;
    }
}

// ---------------------------------------------------------------------------
// Parallel log-sum of picked probabilities (one warp, tree reduction).
// ---------------------------------------------------------------------------
__global__ void logsum_kernel(float* __restrict__ out_scalar)
{
    int lane = threadIdx.x;
    float s = 0.0f;
    for (int k = lane; k < NN; k += 32) s += logf(g_picked[k]);
#pragma unroll
    for (int o = 16; o; o >>= 1) s += __shfl_xor_sync(0xffffffffu, s, o);
    if (lane == 0) *out_scalar = s;
}

extern "C" void kernel_launch(void* const* d_in, const int* in_sizes, int n_in,
                              void* d_out, int out_size)
{
    const float* P = (const float*)d_in[0];    // [D, N] float32
    const int* pos = (const int*)d_in[1];      // [N] int32, sorted
    float* out = (float*)d_out;                // [N*D probs][1 logprob]

    sampler_kernel<<<NN, 256>>>(P, pos, out);
    logsum_kernel<<<1, 32>>>(out + (out_size - 1));
}